// round 15
// baseline (speedup 1.0000x reference)
#include <cuda_runtime.h>
#include <cstdint>

// Problem constants
#define BATCH   2
#define NVIEW   6
#define XD      8
#define YD      8
#define W1D     8
#define W2D     8
#define DIM     128
#define HEADS   4
#define DHEAD   32
#define HDIM    128
#define LWIN    64
#define QTOK    384
#define NBL     128
#define TOKENS  49152
#define R2ROWS  8192
#define EPS     1e-5f
#define FULLMASK 0xffffffffu
#define QSCALE  (0.1767766952966369f * 1.4426950408889634f)

// Scratch: bf16 intermediates packed as uint32 (2 bf16/word, 64 words/row)
__device__ uint32_t g_qp[TOKENS * 64];
__device__ uint32_t g_kp[TOKENS * 64];
__device__ uint32_t g_vp[TOKENS * 64];
__device__ uint32_t g_at[TOKENS * 64];
// Pre-packed transposed weights, 4 slots: wq,wk,wv,wp
__device__ uint32_t g_wt[4 * 128 * 64];

__device__ __forceinline__ uint32_t packbf(float lo, float hi) {
    uint32_t d;
    asm("cvt.rn.bf16x2.f32 %0, %1, %2;" : "=r"(d) : "f"(hi), "f"(lo));
    return d;
}
__device__ __forceinline__ float bflo(uint32_t u) { return __uint_as_float(u << 16); }
__device__ __forceinline__ float bfhi(uint32_t u) { return __uint_as_float(u & 0xffff0000u); }

__device__ __forceinline__ void mma16(float* d, const uint32_t* a, const uint32_t* b) {
    asm volatile("mma.sync.aligned.m16n8k16.row.col.f32.bf16.bf16.f32 "
        "{%0,%1,%2,%3}, {%4,%5,%6,%7}, {%8,%9}, {%0,%1,%2,%3};"
        : "+f"(d[0]), "+f"(d[1]), "+f"(d[2]), "+f"(d[3])
        : "r"(a[0]), "r"(a[1]), "r"(a[2]), "r"(a[3]), "r"(b[0]), "r"(b[1]));
}
__device__ __forceinline__ void ldsm4(uint32_t* r, uint32_t saddr) {
    asm volatile("ldmatrix.sync.aligned.m8n8.x4.shared.b16 {%0,%1,%2,%3}, [%4];"
        : "=r"(r[0]), "=r"(r[1]), "=r"(r[2]), "=r"(r[3]) : "r"(saddr));
}

// ---------------------------------------------------------------------------
// Kernel 0: pre-pack weights. grid=64, block=128.
// ---------------------------------------------------------------------------
__global__ __launch_bounds__(128) void pack_w_kernel(
    const float* __restrict__ wq, const float* __restrict__ wk,
    const float* __restrict__ wv, const float* __restrict__ wp)
{
    int mat   = blockIdx.x >> 4;
    int chunk = blockIdx.x & 15;
    const float* W = (mat == 0) ? wq : (mat == 1) ? wk : (mat == 2) ? wv : wp;
    uint32_t* dst = g_wt + mat * 8192;
    #pragma unroll
    for (int it = 0; it < 4; ++it) {
        int i = chunk * 512 + it * 128 + threadIdx.x;
        int k2 = i >> 7, n = i & 127;
        dst[n * 64 + k2] = packbf(W[(2 * k2) * 128 + n], W[(2 * k2 + 1) * 128 + n]);
    }
}

// ---------------------------------------------------------------------------
// Kernel 1: fold + LayerNorm + projection GEMM (R14 exact).
// 2 tiles of 64 rows per CTA. grid = (384, 3), block = 256.
// ---------------------------------------------------------------------------
#define XS_WSTR 68
#define XS_BSTR 272
#define WT_WOFF (64 * XS_WSTR)
#define WT_BOFF (64 * XS_BSTR)
#define K1_SMEM ((64 + 128) * XS_BSTR)

__global__ __launch_bounds__(256, 3) void ln_proj_mma(
    const float* __restrict__ q, const float* __restrict__ k, const float* __restrict__ v,
    const float* __restrict__ lnq_g, const float* __restrict__ lnq_b,
    const float* __restrict__ lnk_g, const float* __restrict__ lnk_b,
    const float* __restrict__ lnv_g, const float* __restrict__ lnv_b,
    const float* __restrict__ bq, const float* __restrict__ bk,
    const float* __restrict__ bv)
{
    extern __shared__ uint32_t smw[];
    uint32_t sbase = (uint32_t)__cvta_generic_to_shared(smw);

    const float* src; const float* gam; const float* bet;
    const float* bias; uint32_t* dst;
    int mat = blockIdx.y;
    if (mat == 0)      { src = q; gam = lnq_g; bet = lnq_b; bias = bq; dst = g_qp; }
    else if (mat == 1) { src = k; gam = lnk_g; bet = lnk_b; bias = bk; dst = g_kp; }
    else               { src = v; gam = lnv_g; bet = lnv_b; bias = bv; dst = g_vp; }
    const float qmul = (mat == 0) ? QSCALE : 1.0f;

    int tid  = threadIdx.x;
    int warp = tid >> 5;
    int lane = tid & 31;

    {
        const uint4* wsrc = (const uint4*)(g_wt + mat * 8192);
        #pragma unroll
        for (int it = 0; it < 8; ++it) {
            int j  = it * 256 + tid;
            int n  = j >> 4, c4 = j & 15;
            *(uint4*)(smw + WT_WOFF + n * XS_WSTR + c4 * 4) = wsrc[j];
        }
    }

    float4 gg  = ((const float4*)gam)[lane];
    float4 bb4 = ((const float4*)bet)[lane];

    int mg = warp >> 2, ng = warp & 3;
    int g  = lane >> 2, c = lane & 3;
    int khi = (lane & 16) >> 1;
    uint32_t aA0 = sbase + (mg * 32 + (lane & 15)) * XS_BSTR + khi * 2;
    uint32_t aA1 = aA0 + 16 * XS_BSTR;
    uint32_t aB0 = sbase + WT_BOFF
                 + (ng * 32 + (lane & 7) + khi) * XS_BSTR + (lane & 8) * 2;
    uint32_t aB1 = aB0 + 16 * XS_BSTR;

    #pragma unroll
    for (int sub = 0; sub < 2; ++sub) {
        int row0 = blockIdx.x * 128 + sub * 64;

        int bIdx = row0 / (LWIN * QTOK);
        int rem  = row0 % (LWIN * QTOK);
        int l = rem / QTOK;
        int t = rem % QTOK;
        int nv = t >> 6;
        int x = l >> 3, y = l & 7;
        const float* srcBase = src +
            (size_t)((((bIdx * NVIEW + nv) * XD + x) * YD + y)) * (W1D * W2D * DIM);

        __syncthreads();

        #pragma unroll
        for (int it = 0; it < 8; ++it) {
            int rloc = it * 8 + warp;
            float4 xv = ((const float4*)(srcBase + rloc * DIM))[lane];
            float s  = xv.x + xv.y + xv.z + xv.w;
            float ss = xv.x * xv.x + xv.y * xv.y + xv.z * xv.z + xv.w * xv.w;
            #pragma unroll
            for (int o = 16; o; o >>= 1) {
                s  += __shfl_xor_sync(FULLMASK, s,  o);
                ss += __shfl_xor_sync(FULLMASK, ss, o);
            }
            float mu  = s * (1.0f / 128.0f);
            float var = ss * (1.0f / 128.0f) - mu * mu;
            float rs  = rsqrtf(var + EPS);
            float o0 = (xv.x - mu) * rs * gg.x + bb4.x;
            float o1 = (xv.y - mu) * rs * gg.y + bb4.y;
            float o2 = (xv.z - mu) * rs * gg.z + bb4.z;
            float o3 = (xv.w - mu) * rs * gg.w + bb4.w;
            smw[rloc * XS_WSTR + lane * 2    ] = packbf(o0, o1);
            smw[rloc * XS_WSTR + lane * 2 + 1] = packbf(o2, o3);
        }
        __syncthreads();

        float acc[2][4][4];
        #pragma unroll
        for (int mt = 0; mt < 2; ++mt)
            #pragma unroll
            for (int nt = 0; nt < 4; ++nt)
                { acc[mt][nt][0]=0.f; acc[mt][nt][1]=0.f; acc[mt][nt][2]=0.f; acc[mt][nt][3]=0.f; }

        #pragma unroll
        for (int kst = 0; kst < 8; ++kst) {
            uint32_t a0[4], a1[4], b0[4], b1[4];
            ldsm4(a0, aA0 + kst * 32);
            ldsm4(a1, aA1 + kst * 32);
            ldsm4(b0, aB0 + kst * 32);
            ldsm4(b1, aB1 + kst * 32);
            mma16(acc[0][0], a0, b0);     mma16(acc[0][1], a0, b0 + 2);
            mma16(acc[0][2], a0, b1);     mma16(acc[0][3], a0, b1 + 2);
            mma16(acc[1][0], a1, b0);     mma16(acc[1][1], a1, b0 + 2);
            mma16(acc[1][2], a1, b1);     mma16(acc[1][3], a1, b1 + 2);
        }

        #pragma unroll
        for (int nt = 0; nt < 4; ++nt) {
            int col = ng * 32 + nt * 8 + c * 2;
            float2 bv2 = *(const float2*)(bias + col);
            int wcol = ng * 16 + nt * 4 + c;
            #pragma unroll
            for (int mt = 0; mt < 2; ++mt) {
                int rr = row0 + mg * 32 + mt * 16 + g;
                dst[(size_t)rr * 64 + wcol] =
                    packbf((acc[mt][nt][0] + bv2.x) * qmul, (acc[mt][nt][1] + bv2.y) * qmul);
                dst[(size_t)(rr + 8) * 64 + wcol] =
                    packbf((acc[mt][nt][2] + bv2.x) * qmul, (acc[mt][nt][3] + bv2.y) * qmul);
            }
        }
    }
}

// ---------------------------------------------------------------------------
// Kernel 2: flash attention (R10/R14 exact). One CTA per (b,l,head).
// ---------------------------------------------------------------------------
#define KS_WSTR 20
#define KS_BSTR 80
#define VT_WOFF (QTOK * KS_WSTR)
#define VT_BOFF (QTOK * KS_BSTR)
#define VT_WSTR 196
#define VT_BSTR 784
#define K2_SMEM (VT_BOFF + 32 * VT_BSTR)

__global__ __launch_bounds__(768, 1) void attn_mma()
{
    extern __shared__ uint32_t smw[];
    uint32_t sbase = (uint32_t)__cvta_generic_to_shared(smw);

    int bx = blockIdx.x;
    int bl = bx >> 2;
    int m  = bx & 3;
    size_t base_w = (size_t)bl * QTOK * 64 + m * 16;

    int tid = threadIdx.x, warp = tid >> 5, lane = tid & 31;
    int g = lane >> 2, c = lane & 3;

    #pragma unroll
    for (int it = 0; it < 2; ++it) {
        int i = it * 768 + tid;
        int row = i >> 2, c4 = i & 3;
        uint4 u = ((const uint4*)(g_kp + base_w + (size_t)row * 64))[c4];
        *(uint4*)(smw + row * KS_WSTR + c4 * 4) = u;
    }
    {
        int i = tid;
        int r2 = i >> 2, c4 = i & 3;
        uint4 u0 = ((const uint4*)(g_vp + base_w + (size_t)(2 * r2)     * 64))[c4];
        uint4 u1 = ((const uint4*)(g_vp + base_w + (size_t)(2 * r2 + 1) * 64))[c4];
        int w0 = c4 * 4;
        smw[VT_WOFF + (2*w0    ) * VT_WSTR + r2] = __byte_perm(u0.x, u1.x, 0x5410);
        smw[VT_WOFF + (2*w0 + 1) * VT_WSTR + r2] = __byte_perm(u0.x, u1.x, 0x7632);
        smw[VT_WOFF + (2*w0 + 2) * VT_WSTR + r2] = __byte_perm(u0.y, u1.y, 0x5410);
        smw[VT_WOFF + (2*w0 + 3) * VT_WSTR + r2] = __byte_perm(u0.y, u1.y, 0x7632);
        smw[VT_WOFF + (2*w0 + 4) * VT_WSTR + r2] = __byte_perm(u0.z, u1.z, 0x5410);
        smw[VT_WOFF + (2*w0 + 5) * VT_WSTR + r2] = __byte_perm(u0.z, u1.z, 0x7632);
        smw[VT_WOFF + (2*w0 + 6) * VT_WSTR + r2] = __byte_perm(u0.w, u1.w, 0x5410);
        smw[VT_WOFF + (2*w0 + 7) * VT_WSTR + r2] = __byte_perm(u0.w, u1.w, 0x7632);
    }

    int q0 = warp * 16;
    uint32_t qa[2][4];
    {
        const uint32_t* qr0 = g_qp + base_w + (size_t)(q0 + g) * 64;
        const uint32_t* qr1 = g_qp + base_w + (size_t)(q0 + g + 8) * 64;
        #pragma unroll
        for (int kst = 0; kst < 2; ++kst) {
            qa[kst][0] = qr0[kst * 8 + c    ];
            qa[kst][1] = qr1[kst * 8 + c    ];
            qa[kst][2] = qr0[kst * 8 + c + 4];
            qa[kst][3] = qr1[kst * 8 + c + 4];
        }
    }
    __syncthreads();

    float o[4][4];
    #pragma unroll
    for (int nt = 0; nt < 4; ++nt)
        { o[nt][0]=0.f; o[nt][1]=0.f; o[nt][2]=0.f; o[nt][3]=0.f; }
    float lp0 = 0.f, lp1 = 0.f;

    int rhi = (lane & 16) >> 1;
    uint32_t aK = sbase + ((lane & 7) + rhi) * KS_BSTR + (lane & 8) * 2;
    uint32_t aV = sbase + VT_BOFF + ((lane & 7) + rhi) * VT_BSTR + (lane & 8) * 2;

    for (int kc = 0; kc < QTOK; kc += 32) {
        float s[4][4];
        #pragma unroll
        for (int nt = 0; nt < 4; ++nt)
            { s[nt][0]=0.f; s[nt][1]=0.f; s[nt][2]=0.f; s[nt][3]=0.f; }

        #pragma unroll
        for (int kst = 0; kst < 2; ++kst) {
            uint32_t b0[4], b1[4];
            ldsm4(b0, aK + (kc)      * KS_BSTR + kst * 32);
            ldsm4(b1, aK + (kc + 16) * KS_BSTR + kst * 32);
            mma16(s[0], qa[kst], b0);     mma16(s[1], qa[kst], b0 + 2);
            mma16(s[2], qa[kst], b1);     mma16(s[3], qa[kst], b1 + 2);
        }

        #pragma unroll
        for (int nt = 0; nt < 4; ++nt) {
            s[nt][0] = exp2f(s[nt][0]);
            s[nt][1] = exp2f(s[nt][1]);
            s[nt][2] = exp2f(s[nt][2]);
            s[nt][3] = exp2f(s[nt][3]);
            lp0 += s[nt][0] + s[nt][1];
            lp1 += s[nt][2] + s[nt][3];
        }

        #pragma unroll
        for (int kt = 0; kt < 2; ++kt) {
            uint32_t pa[4];
            pa[0] = packbf(s[2*kt  ][0], s[2*kt  ][1]);
            pa[1] = packbf(s[2*kt  ][2], s[2*kt  ][3]);
            pa[2] = packbf(s[2*kt+1][0], s[2*kt+1][1]);
            pa[3] = packbf(s[2*kt+1][2], s[2*kt+1][3]);
            int kbase = kc + kt * 16;
            uint32_t v0[4], v1[4];
            ldsm4(v0, aV                + kbase * 2);
            ldsm4(v1, aV + 16 * VT_BSTR + kbase * 2);
            mma16(o[0], pa, v0);     mma16(o[1], pa, v0 + 2);
            mma16(o[2], pa, v1);     mma16(o[3], pa, v1 + 2);
        }
    }

    lp0 += __shfl_xor_sync(FULLMASK, lp0, 1);
    lp0 += __shfl_xor_sync(FULLMASK, lp0, 2);
    lp1 += __shfl_xor_sync(FULLMASK, lp1, 1);
    lp1 += __shfl_xor_sync(FULLMASK, lp1, 2);

    float inv0 = 1.0f / lp0;
    float inv1 = 1.0f / lp1;
    int r0 = q0 + g;
    #pragma unroll
    for (int nt = 0; nt < 4; ++nt) {
        int wcol = nt * 4 + c;
        g_at[base_w + (size_t)r0 * 64 + wcol]       = packbf(o[nt][0] * inv0, o[nt][1] * inv0);
        g_at[base_w + (size_t)(r0 + 8) * 64 + wcol] = packbf(o[nt][2] * inv1, o[nt][3] * inv1);
    }
}

// ---------------------------------------------------------------------------
// Kernel 3: mean-over-views + output projection + bias + skip.
// 32-row tiles, grid=256, block=256 (8 warps; warp = 16 rows x 32 cols).
// Prologue work per thread halves vs R14; 2x warps hide the gather latency.
// ---------------------------------------------------------------------------
#define WT3_WOFF (32 * XS_WSTR)
#define WT3_BOFF (32 * XS_BSTR)
#define K3_SMEM ((32 + 128) * XS_BSTR)

__global__ __launch_bounds__(256) void out_proj_mma(
    const float* __restrict__ bp,
    const float* __restrict__ skip, float* __restrict__ out)
{
    extern __shared__ uint32_t smw[];
    uint32_t sbase = (uint32_t)__cvta_generic_to_shared(smw);

    int tid  = threadIdx.x;
    int warp = tid >> 5;
    int lane = tid & 31;
    int row0 = blockIdx.x * 32;

    // Wt fill: 2048 uint4 over 256 threads = 8 iters
    {
        const uint4* wsrc = (const uint4*)(g_wt + 3 * 8192);
        #pragma unroll
        for (int it = 0; it < 8; ++it) {
            int j  = it * 256 + tid;
            int n  = j >> 4, c4 = j & 15;
            *(uint4*)(smw + WT3_WOFF + n * XS_WSTR + c4 * 4) = wsrc[j];
        }
    }

    // Xs = mean over n: 512 uint4 ops over 256 threads = 2 iters
    #pragma unroll
    for (int it = 0; it < 2; ++it) {
        int i = it * 256 + tid;
        int rloc = i >> 4, c4 = i & 15;
        int r2 = row0 + rloc;
        int bl = r2 >> 6;
        int wr = r2 & 63;
        const uint4* srcp = (const uint4*)(g_at + (size_t)(bl * QTOK + wr) * 64) + c4;
        float a0=0.f,a1=0.f,a2=0.f,a3=0.f,a4=0.f,a5=0.f,a6=0.f,a7=0.f;
        #pragma unroll
        for (int n = 0; n < NVIEW; ++n) {
            uint4 u = srcp[n * 64 * 16];
            a0 += bflo(u.x); a1 += bfhi(u.x);
            a2 += bflo(u.y); a3 += bfhi(u.y);
            a4 += bflo(u.z); a5 += bfhi(u.z);
            a6 += bflo(u.w); a7 += bfhi(u.w);
        }
        const float iv = 1.0f / 6.0f;
        uint4 ov;
        ov.x = packbf(a0 * iv, a1 * iv);
        ov.y = packbf(a2 * iv, a3 * iv);
        ov.z = packbf(a4 * iv, a5 * iv);
        ov.w = packbf(a6 * iv, a7 * iv);
        *(uint4*)(smw + rloc * XS_WSTR + c4 * 4) = ov;
    }
    __syncthreads();

    // GEMM: warp = 16 rows x 32 cols. mg = warp>>2 (row half), ng = warp&3.
    int mg = warp >> 2, ng = warp & 3;
    int g  = lane >> 2, c = lane & 3;

    float acc[4][4];
    #pragma unroll
    for (int nt = 0; nt < 4; ++nt)
        { acc[nt][0]=0.f; acc[nt][1]=0.f; acc[nt][2]=0.f; acc[nt][3]=0.f; }

    int khi = (lane & 16) >> 1;
    uint32_t aA0 = sbase + (mg * 16 + (lane & 15)) * XS_BSTR + khi * 2;
    uint32_t aB0 = sbase + WT3_BOFF
                 + (ng * 32 + (lane & 7) + khi) * XS_BSTR + (lane & 8) * 2;
    uint32_t aB1 = aB0 + 16 * XS_BSTR;

    #pragma unroll
    for (int kst = 0; kst < 8; ++kst) {
        uint32_t a0[4], b0[4], b1[4];
        ldsm4(a0, aA0 + kst * 32);
        ldsm4(b0, aB0 + kst * 32);
        ldsm4(b1, aB1 + kst * 32);
        mma16(acc[0], a0, b0);     mma16(acc[1], a0, b0 + 2);
        mma16(acc[2], a0, b1);     mma16(acc[3], a0, b1 + 2);
    }

    #pragma unroll
    for (int nt = 0; nt < 4; ++nt) {
        int col = ng * 32 + nt * 8 + c * 2;
        float2 bv2 = *(const float2*)(bp + col);
        int rr = row0 + mg * 16 + g;
        float2 sk0 = *(const float2*)(skip + (size_t)rr * 128 + col);
        float2 sk1 = *(const float2*)(skip + (size_t)(rr + 8) * 128 + col);
        float2 o0 = { acc[nt][0] + bv2.x + sk0.x, acc[nt][1] + bv2.y + sk0.y };
        float2 o1 = { acc[nt][2] + bv2.x + sk1.x, acc[nt][3] + bv2.y + sk1.y };
        *(float2*)(out + (size_t)rr * 128 + col)       = o0;
        *(float2*)(out + (size_t)(rr + 8) * 128 + col) = o1;
    }
}

// ---------------------------------------------------------------------------
extern "C" void kernel_launch(void* const* d_in, const int* in_sizes, int n_in,
                              void* d_out, int out_size)
{
    const float* q     = (const float*)d_in[0];
    const float* k     = (const float*)d_in[1];
    const float* v     = (const float*)d_in[2];
    const float* skip  = (const float*)d_in[3];
    const float* lnq_g = (const float*)d_in[4];
    const float* lnq_b = (const float*)d_in[5];
    const float* lnk_g = (const float*)d_in[6];
    const float* lnk_b = (const float*)d_in[7];
    const float* lnv_g = (const float*)d_in[8];
    const float* lnv_b = (const float*)d_in[9];
    const float* wq    = (const float*)d_in[10];
    const float* bq    = (const float*)d_in[11];
    const float* wk    = (const float*)d_in[12];
    const float* bk    = (const float*)d_in[13];
    const float* wv    = (const float*)d_in[14];
    const float* bv    = (const float*)d_in[15];
    const float* wp    = (const float*)d_in[16];
    const float* bp    = (const float*)d_in[17];
    float* out = (float*)d_out;

    cudaFuncSetAttribute(ln_proj_mma,  cudaFuncAttributeMaxDynamicSharedMemorySize, K1_SMEM);
    cudaFuncSetAttribute(attn_mma,     cudaFuncAttributeMaxDynamicSharedMemorySize, K2_SMEM);
    cudaFuncSetAttribute(out_proj_mma, cudaFuncAttributeMaxDynamicSharedMemorySize, K3_SMEM);

    pack_w_kernel<<<64, 128>>>(wq, wk, wv, wp);

    ln_proj_mma<<<dim3(TOKENS / 128, 3), 256, K1_SMEM>>>(
        q, k, v, lnq_g, lnq_b, lnk_g, lnk_b, lnv_g, lnv_b, bq, bk, bv);

    attn_mma<<<NBL * HEADS, 768, K2_SMEM>>>();

    out_proj_mma<<<R2ROWS / 32, 256, K3_SMEM>>>(bp, skip, out);
}

// round 16
// speedup vs baseline: 1.0132x; 1.0132x over previous
#include <cuda_runtime.h>
#include <cstdint>

// Problem constants
#define BATCH   2
#define NVIEW   6
#define XD      8
#define YD      8
#define W1D     8
#define W2D     8
#define DIM     128
#define HEADS   4
#define DHEAD   32
#define HDIM    128
#define LWIN    64
#define QTOK    384
#define NBL     128
#define TOKENS  49152
#define R2ROWS  8192
#define EPS     1e-5f
#define FULLMASK 0xffffffffu
#define QSCALE  (0.1767766952966369f * 1.4426950408889634f)

// Scratch: bf16 intermediates packed as uint32 (2 bf16/word, 64 words/row)
__device__ uint32_t g_qp[TOKENS * 64];
__device__ uint32_t g_kp[TOKENS * 64];
__device__ uint32_t g_vp[TOKENS * 64];
// g_at now holds the VIEW-AVERAGED attention output: R2ROWS x 64 words
__device__ uint32_t g_at[R2ROWS * 64];
// Pre-packed transposed weights, 4 slots: wq,wk,wv,wp
__device__ uint32_t g_wt[4 * 128 * 64];

__device__ __forceinline__ uint32_t packbf(float lo, float hi) {
    uint32_t d;
    asm("cvt.rn.bf16x2.f32 %0, %1, %2;" : "=r"(d) : "f"(hi), "f"(lo));
    return d;
}

__device__ __forceinline__ void mma16(float* d, const uint32_t* a, const uint32_t* b) {
    asm volatile("mma.sync.aligned.m16n8k16.row.col.f32.bf16.bf16.f32 "
        "{%0,%1,%2,%3}, {%4,%5,%6,%7}, {%8,%9}, {%0,%1,%2,%3};"
        : "+f"(d[0]), "+f"(d[1]), "+f"(d[2]), "+f"(d[3])
        : "r"(a[0]), "r"(a[1]), "r"(a[2]), "r"(a[3]), "r"(b[0]), "r"(b[1]));
}
__device__ __forceinline__ void ldsm4(uint32_t* r, uint32_t saddr) {
    asm volatile("ldmatrix.sync.aligned.m8n8.x4.shared.b16 {%0,%1,%2,%3}, [%4];"
        : "=r"(r[0]), "=r"(r[1]), "=r"(r[2]), "=r"(r[3]) : "r"(saddr));
}

// ---------------------------------------------------------------------------
// Kernel 0: pre-pack weights. grid=64, block=128.
// ---------------------------------------------------------------------------
__global__ __launch_bounds__(128) void pack_w_kernel(
    const float* __restrict__ wq, const float* __restrict__ wk,
    const float* __restrict__ wv, const float* __restrict__ wp)
{
    int mat   = blockIdx.x >> 4;
    int chunk = blockIdx.x & 15;
    const float* W = (mat == 0) ? wq : (mat == 1) ? wk : (mat == 2) ? wv : wp;
    uint32_t* dst = g_wt + mat * 8192;
    #pragma unroll
    for (int it = 0; it < 4; ++it) {
        int i = chunk * 512 + it * 128 + threadIdx.x;
        int k2 = i >> 7, n = i & 127;
        dst[n * 64 + k2] = packbf(W[(2 * k2) * 128 + n], W[(2 * k2 + 1) * 128 + n]);
    }
}

// ---------------------------------------------------------------------------
// Kernel 1: fold + LayerNorm + projection GEMM (R14 exact).
// 2 tiles of 64 rows per CTA. grid = (384, 3), block = 256.
// ---------------------------------------------------------------------------
#define XS_WSTR 68
#define XS_BSTR 272
#define WT_WOFF (64 * XS_WSTR)
#define WT_BOFF (64 * XS_BSTR)
#define K1_SMEM ((64 + 128) * XS_BSTR)

__global__ __launch_bounds__(256, 3) void ln_proj_mma(
    const float* __restrict__ q, const float* __restrict__ k, const float* __restrict__ v,
    const float* __restrict__ lnq_g, const float* __restrict__ lnq_b,
    const float* __restrict__ lnk_g, const float* __restrict__ lnk_b,
    const float* __restrict__ lnv_g, const float* __restrict__ lnv_b,
    const float* __restrict__ bq, const float* __restrict__ bk,
    const float* __restrict__ bv)
{
    extern __shared__ uint32_t smw[];
    uint32_t sbase = (uint32_t)__cvta_generic_to_shared(smw);

    const float* src; const float* gam; const float* bet;
    const float* bias; uint32_t* dst;
    int mat = blockIdx.y;
    if (mat == 0)      { src = q; gam = lnq_g; bet = lnq_b; bias = bq; dst = g_qp; }
    else if (mat == 1) { src = k; gam = lnk_g; bet = lnk_b; bias = bk; dst = g_kp; }
    else               { src = v; gam = lnv_g; bet = lnv_b; bias = bv; dst = g_vp; }
    const float qmul = (mat == 0) ? QSCALE : 1.0f;

    int tid  = threadIdx.x;
    int warp = tid >> 5;
    int lane = tid & 31;

    {
        const uint4* wsrc = (const uint4*)(g_wt + mat * 8192);
        #pragma unroll
        for (int it = 0; it < 8; ++it) {
            int j  = it * 256 + tid;
            int n  = j >> 4, c4 = j & 15;
            *(uint4*)(smw + WT_WOFF + n * XS_WSTR + c4 * 4) = wsrc[j];
        }
    }

    float4 gg  = ((const float4*)gam)[lane];
    float4 bb4 = ((const float4*)bet)[lane];

    int mg = warp >> 2, ng = warp & 3;
    int g  = lane >> 2, c = lane & 3;
    int khi = (lane & 16) >> 1;
    uint32_t aA0 = sbase + (mg * 32 + (lane & 15)) * XS_BSTR + khi * 2;
    uint32_t aA1 = aA0 + 16 * XS_BSTR;
    uint32_t aB0 = sbase + WT_BOFF
                 + (ng * 32 + (lane & 7) + khi) * XS_BSTR + (lane & 8) * 2;
    uint32_t aB1 = aB0 + 16 * XS_BSTR;

    #pragma unroll
    for (int sub = 0; sub < 2; ++sub) {
        int row0 = blockIdx.x * 128 + sub * 64;

        int bIdx = row0 / (LWIN * QTOK);
        int rem  = row0 % (LWIN * QTOK);
        int l = rem / QTOK;
        int t = rem % QTOK;
        int nv = t >> 6;
        int x = l >> 3, y = l & 7;
        const float* srcBase = src +
            (size_t)((((bIdx * NVIEW + nv) * XD + x) * YD + y)) * (W1D * W2D * DIM);

        __syncthreads();

        #pragma unroll
        for (int it = 0; it < 8; ++it) {
            int rloc = it * 8 + warp;
            float4 xv = ((const float4*)(srcBase + rloc * DIM))[lane];
            float s  = xv.x + xv.y + xv.z + xv.w;
            float ss = xv.x * xv.x + xv.y * xv.y + xv.z * xv.z + xv.w * xv.w;
            #pragma unroll
            for (int o = 16; o; o >>= 1) {
                s  += __shfl_xor_sync(FULLMASK, s,  o);
                ss += __shfl_xor_sync(FULLMASK, ss, o);
            }
            float mu  = s * (1.0f / 128.0f);
            float var = ss * (1.0f / 128.0f) - mu * mu;
            float rs  = rsqrtf(var + EPS);
            float o0 = (xv.x - mu) * rs * gg.x + bb4.x;
            float o1 = (xv.y - mu) * rs * gg.y + bb4.y;
            float o2 = (xv.z - mu) * rs * gg.z + bb4.z;
            float o3 = (xv.w - mu) * rs * gg.w + bb4.w;
            smw[rloc * XS_WSTR + lane * 2    ] = packbf(o0, o1);
            smw[rloc * XS_WSTR + lane * 2 + 1] = packbf(o2, o3);
        }
        __syncthreads();

        float acc[2][4][4];
        #pragma unroll
        for (int mt = 0; mt < 2; ++mt)
            #pragma unroll
            for (int nt = 0; nt < 4; ++nt)
                { acc[mt][nt][0]=0.f; acc[mt][nt][1]=0.f; acc[mt][nt][2]=0.f; acc[mt][nt][3]=0.f; }

        #pragma unroll
        for (int kst = 0; kst < 8; ++kst) {
            uint32_t a0[4], a1[4], b0[4], b1[4];
            ldsm4(a0, aA0 + kst * 32);
            ldsm4(a1, aA1 + kst * 32);
            ldsm4(b0, aB0 + kst * 32);
            ldsm4(b1, aB1 + kst * 32);
            mma16(acc[0][0], a0, b0);     mma16(acc[0][1], a0, b0 + 2);
            mma16(acc[0][2], a0, b1);     mma16(acc[0][3], a0, b1 + 2);
            mma16(acc[1][0], a1, b0);     mma16(acc[1][1], a1, b0 + 2);
            mma16(acc[1][2], a1, b1);     mma16(acc[1][3], a1, b1 + 2);
        }

        #pragma unroll
        for (int nt = 0; nt < 4; ++nt) {
            int col = ng * 32 + nt * 8 + c * 2;
            float2 bv2 = *(const float2*)(bias + col);
            int wcol = ng * 16 + nt * 4 + c;
            #pragma unroll
            for (int mt = 0; mt < 2; ++mt) {
                int rr = row0 + mg * 32 + mt * 16 + g;
                dst[(size_t)rr * 64 + wcol] =
                    packbf((acc[mt][nt][0] + bv2.x) * qmul, (acc[mt][nt][1] + bv2.y) * qmul);
                dst[(size_t)(rr + 8) * 64 + wcol] =
                    packbf((acc[mt][nt][2] + bv2.x) * qmul, (acc[mt][nt][3] + bv2.y) * qmul);
            }
        }
    }
}

// ---------------------------------------------------------------------------
// Kernel 2: flash attention + FUSED view-mean epilogue.
// One CTA per (b,l,head), 768 threads. After the main loop, normalized fp32
// O tiles go to smem (reused K/V space, stride 34 f32), then 6-view mean is
// reduced in-CTA and the averaged result written to g_at (64 rows/window).
// ---------------------------------------------------------------------------
#define KS_WSTR 20
#define KS_BSTR 80
#define VT_WOFF (QTOK * KS_WSTR)
#define VT_BOFF (QTOK * KS_BSTR)
#define VT_WSTR 196
#define VT_BSTR 784
#define K2_SMEM (VT_BOFF + 32 * VT_BSTR)
#define RED_STR 34   // fp32 stride for the reduction buffer (384 x 34 = 52224 B)

__global__ __launch_bounds__(768, 1) void attn_mma()
{
    extern __shared__ uint32_t smw[];
    float* sred = (float*)smw;
    uint32_t sbase = (uint32_t)__cvta_generic_to_shared(smw);

    int bx = blockIdx.x;
    int bl = bx >> 2;
    int m  = bx & 3;
    size_t base_w = (size_t)bl * QTOK * 64 + m * 16;   // qkv head slice

    int tid = threadIdx.x, warp = tid >> 5, lane = tid & 31;
    int g = lane >> 2, c = lane & 3;

    #pragma unroll
    for (int it = 0; it < 2; ++it) {
        int i = it * 768 + tid;
        int row = i >> 2, c4 = i & 3;
        uint4 u = ((const uint4*)(g_kp + base_w + (size_t)row * 64))[c4];
        *(uint4*)(smw + row * KS_WSTR + c4 * 4) = u;
    }
    {
        int i = tid;
        int r2 = i >> 2, c4 = i & 3;
        uint4 u0 = ((const uint4*)(g_vp + base_w + (size_t)(2 * r2)     * 64))[c4];
        uint4 u1 = ((const uint4*)(g_vp + base_w + (size_t)(2 * r2 + 1) * 64))[c4];
        int w0 = c4 * 4;
        smw[VT_WOFF + (2*w0    ) * VT_WSTR + r2] = __byte_perm(u0.x, u1.x, 0x5410);
        smw[VT_WOFF + (2*w0 + 1) * VT_WSTR + r2] = __byte_perm(u0.x, u1.x, 0x7632);
        smw[VT_WOFF + (2*w0 + 2) * VT_WSTR + r2] = __byte_perm(u0.y, u1.y, 0x5410);
        smw[VT_WOFF + (2*w0 + 3) * VT_WSTR + r2] = __byte_perm(u0.y, u1.y, 0x7632);
        smw[VT_WOFF + (2*w0 + 4) * VT_WSTR + r2] = __byte_perm(u0.z, u1.z, 0x5410);
        smw[VT_WOFF + (2*w0 + 5) * VT_WSTR + r2] = __byte_perm(u0.z, u1.z, 0x7632);
        smw[VT_WOFF + (2*w0 + 6) * VT_WSTR + r2] = __byte_perm(u0.w, u1.w, 0x5410);
        smw[VT_WOFF + (2*w0 + 7) * VT_WSTR + r2] = __byte_perm(u0.w, u1.w, 0x7632);
    }

    int q0 = warp * 16;
    uint32_t qa[2][4];
    {
        const uint32_t* qr0 = g_qp + base_w + (size_t)(q0 + g) * 64;
        const uint32_t* qr1 = g_qp + base_w + (size_t)(q0 + g + 8) * 64;
        #pragma unroll
        for (int kst = 0; kst < 2; ++kst) {
            qa[kst][0] = qr0[kst * 8 + c    ];
            qa[kst][1] = qr1[kst * 8 + c    ];
            qa[kst][2] = qr0[kst * 8 + c + 4];
            qa[kst][3] = qr1[kst * 8 + c + 4];
        }
    }
    __syncthreads();

    float o[4][4];
    #pragma unroll
    for (int nt = 0; nt < 4; ++nt)
        { o[nt][0]=0.f; o[nt][1]=0.f; o[nt][2]=0.f; o[nt][3]=0.f; }
    float lp0 = 0.f, lp1 = 0.f;

    int rhi = (lane & 16) >> 1;
    uint32_t aK = sbase + ((lane & 7) + rhi) * KS_BSTR + (lane & 8) * 2;
    uint32_t aV = sbase + VT_BOFF + ((lane & 7) + rhi) * VT_BSTR + (lane & 8) * 2;

    for (int kc = 0; kc < QTOK; kc += 32) {
        float s[4][4];
        #pragma unroll
        for (int nt = 0; nt < 4; ++nt)
            { s[nt][0]=0.f; s[nt][1]=0.f; s[nt][2]=0.f; s[nt][3]=0.f; }

        #pragma unroll
        for (int kst = 0; kst < 2; ++kst) {
            uint32_t b0[4], b1[4];
            ldsm4(b0, aK + (kc)      * KS_BSTR + kst * 32);
            ldsm4(b1, aK + (kc + 16) * KS_BSTR + kst * 32);
            mma16(s[0], qa[kst], b0);     mma16(s[1], qa[kst], b0 + 2);
            mma16(s[2], qa[kst], b1);     mma16(s[3], qa[kst], b1 + 2);
        }

        #pragma unroll
        for (int nt = 0; nt < 4; ++nt) {
            s[nt][0] = exp2f(s[nt][0]);
            s[nt][1] = exp2f(s[nt][1]);
            s[nt][2] = exp2f(s[nt][2]);
            s[nt][3] = exp2f(s[nt][3]);
            lp0 += s[nt][0] + s[nt][1];
            lp1 += s[nt][2] + s[nt][3];
        }

        #pragma unroll
        for (int kt = 0; kt < 2; ++kt) {
            uint32_t pa[4];
            pa[0] = packbf(s[2*kt  ][0], s[2*kt  ][1]);
            pa[1] = packbf(s[2*kt  ][2], s[2*kt  ][3]);
            pa[2] = packbf(s[2*kt+1][0], s[2*kt+1][1]);
            pa[3] = packbf(s[2*kt+1][2], s[2*kt+1][3]);
            int kbase = kc + kt * 16;
            uint32_t v0[4], v1[4];
            ldsm4(v0, aV                + kbase * 2);
            ldsm4(v1, aV + 16 * VT_BSTR + kbase * 2);
            mma16(o[0], pa, v0);     mma16(o[1], pa, v0 + 2);
            mma16(o[2], pa, v1);     mma16(o[3], pa, v1 + 2);
        }
    }

    lp0 += __shfl_xor_sync(FULLMASK, lp0, 1);
    lp0 += __shfl_xor_sync(FULLMASK, lp0, 2);
    lp1 += __shfl_xor_sync(FULLMASK, lp1, 1);
    lp1 += __shfl_xor_sync(FULLMASK, lp1, 2);

    float inv0 = 1.0f / lp0;
    float inv1 = 1.0f / lp1;

    // All warps done reading K/V smem before we overwrite it
    __syncthreads();

    // Dump normalized fp32 O tiles to the reduction buffer
    int r0 = q0 + g;
    #pragma unroll
    for (int nt = 0; nt < 4; ++nt) {
        int col = nt * 8 + c * 2;
        float2 v0 = { o[nt][0] * inv0, o[nt][1] * inv0 };
        float2 v1 = { o[nt][2] * inv1, o[nt][3] * inv1 };
        *(float2*)(sred + (size_t)r0 * RED_STR + col)       = v0;
        *(float2*)(sred + (size_t)(r0 + 8) * RED_STR + col) = v1;
    }
    __syncthreads();

    // Mean over the 6 views (fp32), pack bf16, write averaged g_at
    for (int i = tid; i < 64 * 16; i += 768) {
        int w  = i >> 4;     // window-local token 0..63
        int cp = i & 15;     // bf16x2 word within the 32-col head slice
        float a0 = 0.f, a1 = 0.f;
        #pragma unroll
        for (int n = 0; n < NVIEW; ++n) {
            float2 t = *(const float2*)(sred + (size_t)(n * 64 + w) * RED_STR + cp * 2);
            a0 += t.x; a1 += t.y;
        }
        g_at[(size_t)(bl * 64 + w) * 64 + m * 16 + cp] =
            packbf(a0 * (1.0f / 6.0f), a1 * (1.0f / 6.0f));
    }
}

// ---------------------------------------------------------------------------
// Kernel 3: output projection + bias + skip. X load is now a CONTIGUOUS copy
// (mean already done in attn). 32-row tiles, grid=256, block=128.
// ---------------------------------------------------------------------------
#define WT3_WOFF (32 * XS_WSTR)
#define WT3_BOFF (32 * XS_BSTR)
#define K3_SMEM ((32 + 128) * XS_BSTR)

__global__ __launch_bounds__(128) void out_proj_mma(
    const float* __restrict__ bp,
    const float* __restrict__ skip, float* __restrict__ out)
{
    extern __shared__ uint32_t smw[];
    uint32_t sbase = (uint32_t)__cvta_generic_to_shared(smw);

    int tid  = threadIdx.x;
    int warp = tid >> 5;
    int lane = tid & 31;
    int row0 = blockIdx.x * 32;

    {
        const uint4* wsrc = (const uint4*)(g_wt + 3 * 8192);
        #pragma unroll
        for (int it = 0; it < 16; ++it) {
            int j  = it * 128 + tid;
            int n  = j >> 4, c4 = j & 15;
            *(uint4*)(smw + WT3_WOFF + n * XS_WSTR + c4 * 4) = wsrc[j];
        }
    }

    // Xs: straight contiguous copy of pre-averaged rows (512 uint4 / 128 thr)
    {
        const uint4* srcp = (const uint4*)(g_at + (size_t)row0 * 64);
        #pragma unroll
        for (int it = 0; it < 4; ++it) {
            int i = it * 128 + tid;
            int rloc = i >> 4, c4 = i & 15;
            *(uint4*)(smw + rloc * XS_WSTR + c4 * 4) = srcp[i];
        }
    }
    __syncthreads();

    int ng = warp;
    int g  = lane >> 2, c = lane & 3;

    float acc[2][4][4];
    #pragma unroll
    for (int mt = 0; mt < 2; ++mt)
        #pragma unroll
        for (int nt = 0; nt < 4; ++nt)
            { acc[mt][nt][0]=0.f; acc[mt][nt][1]=0.f; acc[mt][nt][2]=0.f; acc[mt][nt][3]=0.f; }

    int khi = (lane & 16) >> 1;
    uint32_t aA0 = sbase + (lane & 15) * XS_BSTR + khi * 2;
    uint32_t aA1 = aA0 + 16 * XS_BSTR;
    uint32_t aB0 = sbase + WT3_BOFF
                 + (ng * 32 + (lane & 7) + khi) * XS_BSTR + (lane & 8) * 2;
    uint32_t aB1 = aB0 + 16 * XS_BSTR;

    #pragma unroll
    for (int kst = 0; kst < 8; ++kst) {
        uint32_t a0[4], a1[4], b0[4], b1[4];
        ldsm4(a0, aA0 + kst * 32);
        ldsm4(a1, aA1 + kst * 32);
        ldsm4(b0, aB0 + kst * 32);
        ldsm4(b1, aB1 + kst * 32);
        mma16(acc[0][0], a0, b0);     mma16(acc[0][1], a0, b0 + 2);
        mma16(acc[0][2], a0, b1);     mma16(acc[0][3], a0, b1 + 2);
        mma16(acc[1][0], a1, b0);     mma16(acc[1][1], a1, b0 + 2);
        mma16(acc[1][2], a1, b1);     mma16(acc[1][3], a1, b1 + 2);
    }

    #pragma unroll
    for (int nt = 0; nt < 4; ++nt) {
        int col = ng * 32 + nt * 8 + c * 2;
        float2 bv2 = *(const float2*)(bp + col);
        #pragma unroll
        for (int mt = 0; mt < 2; ++mt) {
            int rr = row0 + mt * 16 + g;
            float2 sk0 = *(const float2*)(skip + (size_t)rr * 128 + col);
            float2 sk1 = *(const float2*)(skip + (size_t)(rr + 8) * 128 + col);
            float2 o0 = { acc[mt][nt][0] + bv2.x + sk0.x, acc[mt][nt][1] + bv2.y + sk0.y };
            float2 o1 = { acc[mt][nt][2] + bv2.x + sk1.x, acc[mt][nt][3] + bv2.y + sk1.y };
            *(float2*)(out + (size_t)rr * 128 + col)       = o0;
            *(float2*)(out + (size_t)(rr + 8) * 128 + col) = o1;
        }
    }
}

// ---------------------------------------------------------------------------
extern "C" void kernel_launch(void* const* d_in, const int* in_sizes, int n_in,
                              void* d_out, int out_size)
{
    const float* q     = (const float*)d_in[0];
    const float* k     = (const float*)d_in[1];
    const float* v     = (const float*)d_in[2];
    const float* skip  = (const float*)d_in[3];
    const float* lnq_g = (const float*)d_in[4];
    const float* lnq_b = (const float*)d_in[5];
    const float* lnk_g = (const float*)d_in[6];
    const float* lnk_b = (const float*)d_in[7];
    const float* lnv_g = (const float*)d_in[8];
    const float* lnv_b = (const float*)d_in[9];
    const float* wq    = (const float*)d_in[10];
    const float* bq    = (const float*)d_in[11];
    const float* wk    = (const float*)d_in[12];
    const float* bk    = (const float*)d_in[13];
    const float* wv    = (const float*)d_in[14];
    const float* bv    = (const float*)d_in[15];
    const float* wp    = (const float*)d_in[16];
    const float* bp    = (const float*)d_in[17];
    float* out = (float*)d_out;

    cudaFuncSetAttribute(ln_proj_mma,  cudaFuncAttributeMaxDynamicSharedMemorySize, K1_SMEM);
    cudaFuncSetAttribute(attn_mma,     cudaFuncAttributeMaxDynamicSharedMemorySize, K2_SMEM);
    cudaFuncSetAttribute(out_proj_mma, cudaFuncAttributeMaxDynamicSharedMemorySize, K3_SMEM);

    pack_w_kernel<<<64, 128>>>(wq, wk, wv, wp);

    ln_proj_mma<<<dim3(TOKENS / 128, 3), 256, K1_SMEM>>>(
        q, k, v, lnq_g, lnq_b, lnk_g, lnk_b, lnv_g, lnv_b, bq, bk, bv);

    attn_mma<<<NBL * HEADS, 768, K2_SMEM>>>();

    out_proj_mma<<<R2ROWS / 32, 128, K3_SMEM>>>(bp, skip, out);
}

// round 17
// speedup vs baseline: 1.0231x; 1.0097x over previous
#include <cuda_runtime.h>
#include <cstdint>

// Problem constants
#define BATCH   2
#define NVIEW   6
#define XD      8
#define YD      8
#define W1D     8
#define W2D     8
#define DIM     128
#define HEADS   4
#define DHEAD   32
#define HDIM    128
#define LWIN    64
#define QTOK    384
#define NBL     128
#define TOKENS  49152
#define R2ROWS  8192
#define EPS     1e-5f
#define FULLMASK 0xffffffffu
#define QSCALE  (0.1767766952966369f * 1.4426950408889634f)

// Scratch: packed 16-bit intermediates as uint32 (2 vals/word, 64 words/row)
// q,k: bf16. v: f16 (feeds the f16 O-mma).
__device__ uint32_t g_qp[TOKENS * 64];
__device__ uint32_t g_kp[TOKENS * 64];
__device__ uint32_t g_vp[TOKENS * 64];
// View-averaged attention output: R2ROWS x 64 words (bf16)
__device__ uint32_t g_at[R2ROWS * 64];
// Pre-packed transposed weights, 4 slots: wq,wk,wv,wp
__device__ uint32_t g_wt[4 * 128 * 64];

__device__ __forceinline__ uint32_t packbf(float lo, float hi) {
    uint32_t d;
    asm("cvt.rn.bf16x2.f32 %0, %1, %2;" : "=r"(d) : "f"(hi), "f"(lo));
    return d;
}
__device__ __forceinline__ uint32_t packh(float lo, float hi) {
    uint32_t d;
    asm("cvt.rn.f16x2.f32 %0, %1, %2;" : "=r"(d) : "f"(hi), "f"(lo));
    return d;
}
__device__ __forceinline__ uint32_t exp2h2(uint32_t x) {
    uint32_t d;
    asm("ex2.approx.f16x2 %0, %1;" : "=r"(d) : "r"(x));
    return d;
}

// bf16 mma
__device__ __forceinline__ void mma16(float* d, const uint32_t* a, const uint32_t* b) {
    asm volatile("mma.sync.aligned.m16n8k16.row.col.f32.bf16.bf16.f32 "
        "{%0,%1,%2,%3}, {%4,%5,%6,%7}, {%8,%9}, {%0,%1,%2,%3};"
        : "+f"(d[0]), "+f"(d[1]), "+f"(d[2]), "+f"(d[3])
        : "r"(a[0]), "r"(a[1]), "r"(a[2]), "r"(a[3]), "r"(b[0]), "r"(b[1]));
}
// f16 mma
__device__ __forceinline__ void mma16h(float* d, const uint32_t* a, const uint32_t* b) {
    asm volatile("mma.sync.aligned.m16n8k16.row.col.f32.f16.f16.f32 "
        "{%0,%1,%2,%3}, {%4,%5,%6,%7}, {%8,%9}, {%0,%1,%2,%3};"
        : "+f"(d[0]), "+f"(d[1]), "+f"(d[2]), "+f"(d[3])
        : "r"(a[0]), "r"(a[1]), "r"(a[2]), "r"(a[3]), "r"(b[0]), "r"(b[1]));
}
__device__ __forceinline__ void ldsm4(uint32_t* r, uint32_t saddr) {
    asm volatile("ldmatrix.sync.aligned.m8n8.x4.shared.b16 {%0,%1,%2,%3}, [%4];"
        : "=r"(r[0]), "=r"(r[1]), "=r"(r[2]), "=r"(r[3]) : "r"(saddr));
}

// ---------------------------------------------------------------------------
// Kernel 0: pre-pack weights. grid=64, block=128.
// ---------------------------------------------------------------------------
__global__ __launch_bounds__(128) void pack_w_kernel(
    const float* __restrict__ wq, const float* __restrict__ wk,
    const float* __restrict__ wv, const float* __restrict__ wp)
{
    int mat   = blockIdx.x >> 4;
    int chunk = blockIdx.x & 15;
    const float* W = (mat == 0) ? wq : (mat == 1) ? wk : (mat == 2) ? wv : wp;
    uint32_t* dst = g_wt + mat * 8192;
    #pragma unroll
    for (int it = 0; it < 4; ++it) {
        int i = chunk * 512 + it * 128 + threadIdx.x;
        int k2 = i >> 7, n = i & 127;
        dst[n * 64 + k2] = packbf(W[(2 * k2) * 128 + n], W[(2 * k2 + 1) * 128 + n]);
    }
}

// ---------------------------------------------------------------------------
// Kernel 1: fold + LayerNorm + projection GEMM. 2 tiles of 64 rows per CTA.
// V output stored as f16 (for attn's f16 O-mma); q/k stay bf16.
// ---------------------------------------------------------------------------
#define XS_WSTR 68
#define XS_BSTR 272
#define WT_WOFF (64 * XS_WSTR)
#define WT_BOFF (64 * XS_BSTR)
#define K1_SMEM ((64 + 128) * XS_BSTR)

__global__ __launch_bounds__(256, 3) void ln_proj_mma(
    const float* __restrict__ q, const float* __restrict__ k, const float* __restrict__ v,
    const float* __restrict__ lnq_g, const float* __restrict__ lnq_b,
    const float* __restrict__ lnk_g, const float* __restrict__ lnk_b,
    const float* __restrict__ lnv_g, const float* __restrict__ lnv_b,
    const float* __restrict__ bq, const float* __restrict__ bk,
    const float* __restrict__ bv)
{
    extern __shared__ uint32_t smw[];
    uint32_t sbase = (uint32_t)__cvta_generic_to_shared(smw);

    const float* src; const float* gam; const float* bet;
    const float* bias; uint32_t* dst;
    int mat = blockIdx.y;
    if (mat == 0)      { src = q; gam = lnq_g; bet = lnq_b; bias = bq; dst = g_qp; }
    else if (mat == 1) { src = k; gam = lnk_g; bet = lnk_b; bias = bk; dst = g_kp; }
    else               { src = v; gam = lnv_g; bet = lnv_b; bias = bv; dst = g_vp; }
    const float qmul = (mat == 0) ? QSCALE : 1.0f;
    const bool  vf16 = (mat == 2);

    int tid  = threadIdx.x;
    int warp = tid >> 5;
    int lane = tid & 31;

    {
        const uint4* wsrc = (const uint4*)(g_wt + mat * 8192);
        #pragma unroll
        for (int it = 0; it < 8; ++it) {
            int j  = it * 256 + tid;
            int n  = j >> 4, c4 = j & 15;
            *(uint4*)(smw + WT_WOFF + n * XS_WSTR + c4 * 4) = wsrc[j];
        }
    }

    float4 gg  = ((const float4*)gam)[lane];
    float4 bb4 = ((const float4*)bet)[lane];

    int mg = warp >> 2, ng = warp & 3;
    int g  = lane >> 2, c = lane & 3;
    int khi = (lane & 16) >> 1;
    uint32_t aA0 = sbase + (mg * 32 + (lane & 15)) * XS_BSTR + khi * 2;
    uint32_t aA1 = aA0 + 16 * XS_BSTR;
    uint32_t aB0 = sbase + WT_BOFF
                 + (ng * 32 + (lane & 7) + khi) * XS_BSTR + (lane & 8) * 2;
    uint32_t aB1 = aB0 + 16 * XS_BSTR;

    #pragma unroll
    for (int sub = 0; sub < 2; ++sub) {
        int row0 = blockIdx.x * 128 + sub * 64;

        int bIdx = row0 / (LWIN * QTOK);
        int rem  = row0 % (LWIN * QTOK);
        int l = rem / QTOK;
        int t = rem % QTOK;
        int nv = t >> 6;
        int x = l >> 3, y = l & 7;
        const float* srcBase = src +
            (size_t)((((bIdx * NVIEW + nv) * XD + x) * YD + y)) * (W1D * W2D * DIM);

        __syncthreads();

        #pragma unroll
        for (int it = 0; it < 8; ++it) {
            int rloc = it * 8 + warp;
            float4 xv = ((const float4*)(srcBase + rloc * DIM))[lane];
            float s  = xv.x + xv.y + xv.z + xv.w;
            float ss = xv.x * xv.x + xv.y * xv.y + xv.z * xv.z + xv.w * xv.w;
            #pragma unroll
            for (int o = 16; o; o >>= 1) {
                s  += __shfl_xor_sync(FULLMASK, s,  o);
                ss += __shfl_xor_sync(FULLMASK, ss, o);
            }
            float mu  = s * (1.0f / 128.0f);
            float var = ss * (1.0f / 128.0f) - mu * mu;
            float rs  = rsqrtf(var + EPS);
            float o0 = (xv.x - mu) * rs * gg.x + bb4.x;
            float o1 = (xv.y - mu) * rs * gg.y + bb4.y;
            float o2 = (xv.z - mu) * rs * gg.z + bb4.z;
            float o3 = (xv.w - mu) * rs * gg.w + bb4.w;
            smw[rloc * XS_WSTR + lane * 2    ] = packbf(o0, o1);
            smw[rloc * XS_WSTR + lane * 2 + 1] = packbf(o2, o3);
        }
        __syncthreads();

        float acc[2][4][4];
        #pragma unroll
        for (int mt = 0; mt < 2; ++mt)
            #pragma unroll
            for (int nt = 0; nt < 4; ++nt)
                { acc[mt][nt][0]=0.f; acc[mt][nt][1]=0.f; acc[mt][nt][2]=0.f; acc[mt][nt][3]=0.f; }

        #pragma unroll
        for (int kst = 0; kst < 8; ++kst) {
            uint32_t a0[4], a1[4], b0[4], b1[4];
            ldsm4(a0, aA0 + kst * 32);
            ldsm4(a1, aA1 + kst * 32);
            ldsm4(b0, aB0 + kst * 32);
            ldsm4(b1, aB1 + kst * 32);
            mma16(acc[0][0], a0, b0);     mma16(acc[0][1], a0, b0 + 2);
            mma16(acc[0][2], a0, b1);     mma16(acc[0][3], a0, b1 + 2);
            mma16(acc[1][0], a1, b0);     mma16(acc[1][1], a1, b0 + 2);
            mma16(acc[1][2], a1, b1);     mma16(acc[1][3], a1, b1 + 2);
        }

        #pragma unroll
        for (int nt = 0; nt < 4; ++nt) {
            int col = ng * 32 + nt * 8 + c * 2;
            float2 bv2 = *(const float2*)(bias + col);
            int wcol = ng * 16 + nt * 4 + c;
            #pragma unroll
            for (int mt = 0; mt < 2; ++mt) {
                int rr = row0 + mg * 32 + mt * 16 + g;
                float p0 = (acc[mt][nt][0] + bv2.x) * qmul;
                float p1 = (acc[mt][nt][1] + bv2.y) * qmul;
                float p2 = (acc[mt][nt][2] + bv2.x) * qmul;
                float p3 = (acc[mt][nt][3] + bv2.y) * qmul;
                dst[(size_t)rr * 64 + wcol]       = vf16 ? packh(p0, p1) : packbf(p0, p1);
                dst[(size_t)(rr + 8) * 64 + wcol] = vf16 ? packh(p2, p3) : packbf(p2, p3);
            }
        }
    }
}

// ---------------------------------------------------------------------------
// Kernel 2: flash attention + fused view-mean.
// P via ex2.approx.f16x2 (2-wide exp), O-mma in f16, row-sum l computed by an
// extra ones-column tile in Vt (dims 32..47: row32=1.0, rest 0).
// ---------------------------------------------------------------------------
#define KS_WSTR 20
#define KS_BSTR 80
#define VT_WOFF (QTOK * KS_WSTR)
#define VT_BOFF (QTOK * KS_BSTR)
#define VT_WSTR 196
#define VT_BSTR 784
#define VT_ROWS 48
#define K2_SMEM (VT_BOFF + VT_ROWS * VT_BSTR)
#define RED_STR 34

__global__ __launch_bounds__(768, 1) void attn_mma()
{
    extern __shared__ uint32_t smw[];
    float* sred = (float*)smw;
    uint32_t sbase = (uint32_t)__cvta_generic_to_shared(smw);

    int bx = blockIdx.x;
    int bl = bx >> 2;
    int m  = bx & 3;
    size_t base_w = (size_t)bl * QTOK * 64 + m * 16;

    int tid = threadIdx.x, warp = tid >> 5, lane = tid & 31;
    int g = lane >> 2, c = lane & 3;

    #pragma unroll
    for (int it = 0; it < 2; ++it) {
        int i = it * 768 + tid;
        int row = i >> 2, c4 = i & 3;
        uint4 u = ((const uint4*)(g_kp + base_w + (size_t)row * 64))[c4];
        *(uint4*)(smw + row * KS_WSTR + c4 * 4) = u;
    }
    {
        int i = tid;
        int r2 = i >> 2, c4 = i & 3;
        uint4 u0 = ((const uint4*)(g_vp + base_w + (size_t)(2 * r2)     * 64))[c4];
        uint4 u1 = ((const uint4*)(g_vp + base_w + (size_t)(2 * r2 + 1) * 64))[c4];
        int w0 = c4 * 4;
        smw[VT_WOFF + (2*w0    ) * VT_WSTR + r2] = __byte_perm(u0.x, u1.x, 0x5410);
        smw[VT_WOFF + (2*w0 + 1) * VT_WSTR + r2] = __byte_perm(u0.x, u1.x, 0x7632);
        smw[VT_WOFF + (2*w0 + 2) * VT_WSTR + r2] = __byte_perm(u0.y, u1.y, 0x5410);
        smw[VT_WOFF + (2*w0 + 3) * VT_WSTR + r2] = __byte_perm(u0.y, u1.y, 0x7632);
        smw[VT_WOFF + (2*w0 + 4) * VT_WSTR + r2] = __byte_perm(u0.z, u1.z, 0x5410);
        smw[VT_WOFF + (2*w0 + 5) * VT_WSTR + r2] = __byte_perm(u0.z, u1.z, 0x7632);
        smw[VT_WOFF + (2*w0 + 6) * VT_WSTR + r2] = __byte_perm(u0.w, u1.w, 0x5410);
        smw[VT_WOFF + (2*w0 + 7) * VT_WSTR + r2] = __byte_perm(u0.w, u1.w, 0x7632);
    }
    // Vt dims 32..47: row 32 = 1.0 (f16x2 {1,1}), rows 33..47 = 0
    for (int i = tid; i < 16 * VT_WSTR; i += 768)
        smw[VT_WOFF + 32 * VT_WSTR + i] = (i < VT_WSTR) ? 0x3C003C00u : 0u;

    int q0 = warp * 16;
    uint32_t qa[2][4];
    {
        const uint32_t* qr0 = g_qp + base_w + (size_t)(q0 + g) * 64;
        const uint32_t* qr1 = g_qp + base_w + (size_t)(q0 + g + 8) * 64;
        #pragma unroll
        for (int kst = 0; kst < 2; ++kst) {
            qa[kst][0] = qr0[kst * 8 + c    ];
            qa[kst][1] = qr1[kst * 8 + c    ];
            qa[kst][2] = qr0[kst * 8 + c + 4];
            qa[kst][3] = qr1[kst * 8 + c + 4];
        }
    }
    __syncthreads();

    float o[5][4];
    #pragma unroll
    for (int nt = 0; nt < 5; ++nt)
        { o[nt][0]=0.f; o[nt][1]=0.f; o[nt][2]=0.f; o[nt][3]=0.f; }

    int rhi = (lane & 16) >> 1;
    uint32_t aK = sbase + ((lane & 7) + rhi) * KS_BSTR + (lane & 8) * 2;
    uint32_t aV = sbase + VT_BOFF + ((lane & 7) + rhi) * VT_BSTR + (lane & 8) * 2;

    for (int kc = 0; kc < QTOK; kc += 32) {
        float s[4][4];
        #pragma unroll
        for (int nt = 0; nt < 4; ++nt)
            { s[nt][0]=0.f; s[nt][1]=0.f; s[nt][2]=0.f; s[nt][3]=0.f; }

        #pragma unroll
        for (int kst = 0; kst < 2; ++kst) {
            uint32_t b0[4], b1[4];
            ldsm4(b0, aK + (kc)      * KS_BSTR + kst * 32);
            ldsm4(b1, aK + (kc + 16) * KS_BSTR + kst * 32);
            mma16(s[0], qa[kst], b0);     mma16(s[1], qa[kst], b0 + 2);
            mma16(s[2], qa[kst], b1);     mma16(s[3], qa[kst], b1 + 2);
        }

        // P = exp2(S) via 2-wide f16 exp; result is directly the f16 A-frag
        #pragma unroll
        for (int kt = 0; kt < 2; ++kt) {
            uint32_t pa[4];
            pa[0] = exp2h2(packh(s[2*kt  ][0], s[2*kt  ][1]));
            pa[1] = exp2h2(packh(s[2*kt  ][2], s[2*kt  ][3]));
            pa[2] = exp2h2(packh(s[2*kt+1][0], s[2*kt+1][1]));
            pa[3] = exp2h2(packh(s[2*kt+1][2], s[2*kt+1][3]));
            int kbase = kc + kt * 16;
            uint32_t v0[4], v1[4], v2[4];
            ldsm4(v0, aV                + kbase * 2);
            ldsm4(v1, aV + 16 * VT_BSTR + kbase * 2);
            ldsm4(v2, aV + 32 * VT_BSTR + kbase * 2);   // dims 32..47 (ones col)
            mma16h(o[0], pa, v0);     mma16h(o[1], pa, v0 + 2);
            mma16h(o[2], pa, v1);     mma16h(o[3], pa, v1 + 2);
            mma16h(o[4], pa, v2);     // col 32 accumulates l
        }
    }

    // l sits in o[4][0] (row g) / o[4][2] (row g+8) of the c==0 lane
    float l0 = __shfl_sync(FULLMASK, o[4][0], lane & ~3);
    float l1 = __shfl_sync(FULLMASK, o[4][2], lane & ~3);
    float inv0 = 1.0f / l0;
    float inv1 = 1.0f / l1;

    __syncthreads();

    // Dump normalized fp32 O tiles to the reduction buffer
    int r0 = q0 + g;
    #pragma unroll
    for (int nt = 0; nt < 4; ++nt) {
        int col = nt * 8 + c * 2;
        float2 v0 = { o[nt][0] * inv0, o[nt][1] * inv0 };
        float2 v1 = { o[nt][2] * inv1, o[nt][3] * inv1 };
        *(float2*)(sred + (size_t)r0 * RED_STR + col)       = v0;
        *(float2*)(sred + (size_t)(r0 + 8) * RED_STR + col) = v1;
    }
    __syncthreads();

    // Mean over the 6 views (fp32), pack bf16, write averaged g_at
    for (int i = tid; i < 64 * 16; i += 768) {
        int w  = i >> 4;
        int cp = i & 15;
        float a0 = 0.f, a1 = 0.f;
        #pragma unroll
        for (int n = 0; n < NVIEW; ++n) {
            float2 t = *(const float2*)(sred + (size_t)(n * 64 + w) * RED_STR + cp * 2);
            a0 += t.x; a1 += t.y;
        }
        g_at[(size_t)(bl * 64 + w) * 64 + m * 16 + cp] =
            packbf(a0 * (1.0f / 6.0f), a1 * (1.0f / 6.0f));
    }
}

// ---------------------------------------------------------------------------
// Kernel 3: output projection + bias + skip (contiguous X copy).
// ---------------------------------------------------------------------------
#define WT3_WOFF (32 * XS_WSTR)
#define WT3_BOFF (32 * XS_BSTR)
#define K3_SMEM ((32 + 128) * XS_BSTR)

__global__ __launch_bounds__(128) void out_proj_mma(
    const float* __restrict__ bp,
    const float* __restrict__ skip, float* __restrict__ out)
{
    extern __shared__ uint32_t smw[];
    uint32_t sbase = (uint32_t)__cvta_generic_to_shared(smw);

    int tid  = threadIdx.x;
    int warp = tid >> 5;
    int lane = tid & 31;
    int row0 = blockIdx.x * 32;

    {
        const uint4* wsrc = (const uint4*)(g_wt + 3 * 8192);
        #pragma unroll
        for (int it = 0; it < 16; ++it) {
            int j  = it * 128 + tid;
            int n  = j >> 4, c4 = j & 15;
            *(uint4*)(smw + WT3_WOFF + n * XS_WSTR + c4 * 4) = wsrc[j];
        }
    }

    {
        const uint4* srcp = (const uint4*)(g_at + (size_t)row0 * 64);
        #pragma unroll
        for (int it = 0; it < 4; ++it) {
            int i = it * 128 + tid;
            int rloc = i >> 4, c4 = i & 15;
            *(uint4*)(smw + rloc * XS_WSTR + c4 * 4) = srcp[i];
        }
    }
    __syncthreads();

    int ng = warp;
    int g  = lane >> 2, c = lane & 3;

    float acc[2][4][4];
    #pragma unroll
    for (int mt = 0; mt < 2; ++mt)
        #pragma unroll
        for (int nt = 0; nt < 4; ++nt)
            { acc[mt][nt][0]=0.f; acc[mt][nt][1]=0.f; acc[mt][nt][2]=0.f; acc[mt][nt][3]=0.f; }

    int khi = (lane & 16) >> 1;
    uint32_t aA0 = sbase + (lane & 15) * XS_BSTR + khi * 2;
    uint32_t aA1 = aA0 + 16 * XS_BSTR;
    uint32_t aB0 = sbase + WT3_BOFF
                 + (ng * 32 + (lane & 7) + khi) * XS_BSTR + (lane & 8) * 2;
    uint32_t aB1 = aB0 + 16 * XS_BSTR;

    #pragma unroll
    for (int kst = 0; kst < 8; ++kst) {
        uint32_t a0[4], a1[4], b0[4], b1[4];
        ldsm4(a0, aA0 + kst * 32);
        ldsm4(a1, aA1 + kst * 32);
        ldsm4(b0, aB0 + kst * 32);
        ldsm4(b1, aB1 + kst * 32);
        mma16(acc[0][0], a0, b0);     mma16(acc[0][1], a0, b0 + 2);
        mma16(acc[0][2], a0, b1);     mma16(acc[0][3], a0, b1 + 2);
        mma16(acc[1][0], a1, b0);     mma16(acc[1][1], a1, b0 + 2);
        mma16(acc[1][2], a1, b1);     mma16(acc[1][3], a1, b1 + 2);
    }

    #pragma unroll
    for (int nt = 0; nt < 4; ++nt) {
        int col = ng * 32 + nt * 8 + c * 2;
        float2 bv2 = *(const float2*)(bp + col);
        #pragma unroll
        for (int mt = 0; mt < 2; ++mt) {
            int rr = row0 + mt * 16 + g;
            float2 sk0 = *(const float2*)(skip + (size_t)rr * 128 + col);
            float2 sk1 = *(const float2*)(skip + (size_t)(rr + 8) * 128 + col);
            float2 o0 = { acc[mt][nt][0] + bv2.x + sk0.x, acc[mt][nt][1] + bv2.y + sk0.y };
            float2 o1 = { acc[mt][nt][2] + bv2.x + sk1.x, acc[mt][nt][3] + bv2.y + sk1.y };
            *(float2*)(out + (size_t)rr * 128 + col)       = o0;
            *(float2*)(out + (size_t)(rr + 8) * 128 + col) = o1;
        }
    }
}

// ---------------------------------------------------------------------------
extern "C" void kernel_launch(void* const* d_in, const int* in_sizes, int n_in,
                              void* d_out, int out_size)
{
    const float* q     = (const float*)d_in[0];
    const float* k     = (const float*)d_in[1];
    const float* v     = (const float*)d_in[2];
    const float* skip  = (const float*)d_in[3];
    const float* lnq_g = (const float*)d_in[4];
    const float* lnq_b = (const float*)d_in[5];
    const float* lnk_g = (const float*)d_in[6];
    const float* lnk_b = (const float*)d_in[7];
    const float* lnv_g = (const float*)d_in[8];
    const float* lnv_b = (const float*)d_in[9];
    const float* wq    = (const float*)d_in[10];
    const float* bq    = (const float*)d_in[11];
    const float* wk    = (const float*)d_in[12];
    const float* bk    = (const float*)d_in[13];
    const float* wv    = (const float*)d_in[14];
    const float* bv    = (const float*)d_in[15];
    const float* wp    = (const float*)d_in[16];
    const float* bp    = (const float*)d_in[17];
    float* out = (float*)d_out;

    cudaFuncSetAttribute(ln_proj_mma,  cudaFuncAttributeMaxDynamicSharedMemorySize, K1_SMEM);
    cudaFuncSetAttribute(attn_mma,     cudaFuncAttributeMaxDynamicSharedMemorySize, K2_SMEM);
    cudaFuncSetAttribute(out_proj_mma, cudaFuncAttributeMaxDynamicSharedMemorySize, K3_SMEM);

    pack_w_kernel<<<64, 128>>>(wq, wk, wv, wp);

    ln_proj_mma<<<dim3(TOKENS / 128, 3), 256, K1_SMEM>>>(
        q, k, v, lnq_g, lnq_b, lnk_g, lnk_b, lnv_g, lnv_b, bq, bk, bv);

    attn_mma<<<NBL * HEADS, 768, K2_SMEM>>>();

    out_proj_mma<<<R2ROWS / 32, 128, K3_SMEM>>>(bp, skip, out);
}